// round 1
// baseline (speedup 1.0000x reference)
#include <cuda_runtime.h>

#define NN 100000
#define EE 3200000
#define FIN 128
#define NBLK 196   // ceil(NN/512)

// ---------------- scratch (static device globals; no allocs) ----------------
__device__ int   g_cnt[NN + 1];
__device__ int   g_off[NN + 1];
__device__ int   g_cur[NN];
__device__ int   g_bsum[NBLK];
__device__ int   g_srcs[EE];
__device__ float g_p[EE];
__device__ float g_xl1[NN * 16];
__device__ float g_xr1[NN * 16];
__device__ float g_lin1[NN * 16];
__device__ float g_h[NN * 16];
__device__ float g_xl2[NN * 8];
__device__ float g_xr2[NN * 8];
__device__ float g_lin2[NN * 8];
__device__ float g_h2[NN * 8];

__device__ __forceinline__ float ex2f(float x) {
    float y; asm("ex2.approx.f32 %0, %1;" : "=f"(y) : "f"(x)); return y;
}

// ---------------- CSR build ----------------
__global__ void k_zero() {
    int i = blockIdx.x * blockDim.x + threadIdx.x;
    if (i <= NN) g_cnt[i] = 0;
}

__global__ void k_hist(const int* __restrict__ dst) {
    int e = blockIdx.x * blockDim.x + threadIdx.x;
    if (e < EE) atomicAdd(&g_cnt[dst[e]], 1);
}

__global__ void k_scan1() {
    int t = threadIdx.x, b = blockIdx.x;
    int i = b * 512 + t;
    int v = (i < NN) ? g_cnt[i] : 0;
    int lane = t & 31, wid = t >> 5;
    int incl = v;
#pragma unroll
    for (int o = 1; o < 32; o <<= 1) {
        int u = __shfl_up_sync(0xffffffffu, incl, o);
        if (lane >= o) incl += u;
    }
    __shared__ int ws[16];
    if (lane == 31) ws[wid] = incl;
    __syncthreads();
    if (t < 16) {
        int x = ws[t];
#pragma unroll
        for (int o = 1; o < 16; o <<= 1) {
            int u = __shfl_up_sync(0x0000ffffu, x, o);
            if (t >= o) x += u;
        }
        ws[t] = x;
    }
    __syncthreads();
    if (wid > 0) incl += ws[wid - 1];
    if (i < NN) g_off[i + 1] = incl;
    if (t == 511) g_bsum[b] = incl;
}

__global__ void k_scan2() {
    // warp-parallel exclusive scan over NBLK block sums
    int l = threadIdx.x;
    const int PER = (NBLK + 31) / 32;  // 7
    int base = l * PER;
    int v[PER];
    int s = 0;
#pragma unroll
    for (int j = 0; j < PER; j++) {
        int idx = base + j;
        int t = (idx < NBLK) ? g_bsum[idx] : 0;
        v[j] = s;        // local exclusive
        s += t;
    }
    int inc = s;
#pragma unroll
    for (int o = 1; o < 32; o <<= 1) {
        int u = __shfl_up_sync(0xffffffffu, inc, o);
        if (l >= o) inc += u;
    }
    int excl = inc - s;
#pragma unroll
    for (int j = 0; j < PER; j++) {
        int idx = base + j;
        if (idx < NBLK) g_bsum[idx] = v[j] + excl;
    }
}

__global__ void k_scan3() {
    int t = threadIdx.x, b = blockIdx.x;
    int i = b * 512 + t;
    if (i < NN) {
        int val = g_off[i + 1] + g_bsum[b];
        g_off[i + 1] = val;
        g_cur[i] = val - g_cnt[i];
    }
    if (i == 0) g_off[0] = 0;
}

__global__ void k_scatter(const int* __restrict__ src, const int* __restrict__ dst) {
    int e = blockIdx.x * blockDim.x + threadIdx.x;
    if (e < EE) {
        int p = atomicAdd(&g_cur[dst[e]], 1);
        g_srcs[p] = src[e];
    }
}

// ---------------- layer-1 node GEMM: xl1 | xr1 | lin1(+blin1) ----------------
__global__ void __launch_bounds__(256) k_gemm1(
    const float* __restrict__ x, const float* __restrict__ Wl,
    const float* __restrict__ Wr, const float* __restrict__ Wlin,
    const float* __restrict__ blin)
{
    __shared__ float sx[32][FIN + 1];
    __shared__ float sw[FIN][48];
    int t = threadIdx.x;
    int rowbase = blockIdx.x * 32;
    for (int idx = t; idx < 32 * FIN; idx += 256) {
        int r = idx >> 7, c = idx & 127;
        int gr = rowbase + r;
        sx[r][c] = (gr < NN) ? x[gr * FIN + c] : 0.f;
    }
    for (int idx = t; idx < FIN * 48; idx += 256) {
        int k = idx / 48, j = idx % 48;
        float v;
        if (j < 16)      v = Wl[k * 16 + j];
        else if (j < 32) v = Wr[k * 16 + j - 16];
        else             v = Wlin[k * 16 + j - 32];
        sw[k][j] = v;
    }
    __syncthreads();
    int r = t >> 3;
    int c0 = (t & 7) * 6;
    float acc[6] = {0.f, 0.f, 0.f, 0.f, 0.f, 0.f};
#pragma unroll 4
    for (int k = 0; k < FIN; k++) {
        float xv = sx[r][k];
#pragma unroll
        for (int j = 0; j < 6; j++) acc[j] = fmaf(xv, sw[k][c0 + j], acc[j]);
    }
    int gr = rowbase + r;
    if (gr < NN) {
#pragma unroll
        for (int j = 0; j < 6; j++) {
            int c = c0 + j;
            if (c < 16)      g_xl1[gr * 16 + c] = acc[j];
            else if (c < 32) g_xr1[gr * 16 + (c - 16)] = acc[j];
            else             g_lin1[gr * 16 + (c - 32)] = acc[j] + blin[c - 32];
        }
    }
}

// ---------------- layer-2 node GEMM: xl2 | xr2 | lin2(+blin2) ----------------
__global__ void __launch_bounds__(256) k_gemm2(
    const float* __restrict__ Wl, const float* __restrict__ Wr,
    const float* __restrict__ Wlin, const float* __restrict__ blin)
{
    __shared__ float sw[16 * 24];
    int t = threadIdx.x;
    for (int idx = t; idx < 16 * 24; idx += 256) {
        int k = idx / 24, j = idx % 24;
        float v;
        if (j < 8)       v = Wl[k * 8 + j];
        else if (j < 16) v = Wr[k * 8 + j - 8];
        else             v = Wlin[k * 8 + j - 16];
        sw[idx] = v;
    }
    __syncthreads();
    int i = blockIdx.x * blockDim.x + t;
    if (i >= NN) return;
    const float4* hp = (const float4*)(g_h + i * 16);
    float4 q0 = hp[0], q1 = hp[1], q2 = hp[2], q3 = hp[3];
    float h[16] = {q0.x, q0.y, q0.z, q0.w, q1.x, q1.y, q1.z, q1.w,
                   q2.x, q2.y, q2.z, q2.w, q3.x, q3.y, q3.z, q3.w};
    float acc[24];
#pragma unroll
    for (int j = 0; j < 24; j++) acc[j] = 0.f;
#pragma unroll
    for (int k = 0; k < 16; k++) {
        float hv = h[k];
#pragma unroll
        for (int j = 0; j < 24; j++) acc[j] = fmaf(hv, sw[k * 24 + j], acc[j]);
    }
#pragma unroll
    for (int j = 0; j < 8; j++) {
        g_xl2[i * 8 + j] = acc[j];
        g_xr2[i * 8 + j] = acc[8 + j];
        g_lin2[i * 8 + j] = acc[16 + j] + blin[j];
    }
}

// ---------------- edge kernel: warp per dst node, both softmaxes fused ------
template <int C>
__device__ __forceinline__ void edge_impl(
    const float* __restrict__ xl, const float* __restrict__ xr,
    const float* __restrict__ att, const float* __restrict__ bias,
    const float* __restrict__ lin, const float* __restrict__ tptr,
    float* __restrict__ out)
{
    int warp = (blockIdx.x * blockDim.x + threadIdx.x) >> 5;
    int lane = threadIdx.x & 31;
    if (warp >= NN) return;
    int beg = g_off[warp], end = g_off[warp + 1];
    float a_att[C], a_xr[C];
#pragma unroll
    for (int c = 0; c < C; c += 4) {
        float4 a = *(const float4*)(att + c);
        float4 b = *(const float4*)(xr + warp * C + c);
        a_att[c] = a.x; a_att[c + 1] = a.y; a_att[c + 2] = a.z; a_att[c + 3] = a.w;
        a_xr[c]  = b.x; a_xr[c + 1]  = b.y; a_xr[c + 2]  = b.z; a_xr[c + 3]  = b.w;
    }
    float tval = tptr[0];
    int deg = end - beg;
    int kend = beg + ((deg + 31) & ~31);

    // pass 1: attention softmax denominator (no max-sub: scores are O(1))
    float S = 0.f;
    for (int k = beg + lane; k < kend; k += 32) {
        bool v = k < end;
        int s = v ? g_srcs[k] : 0;
        float m[C];
        const float4* xp = (const float4*)(xl + s * C);
#pragma unroll
        for (int c = 0; c < C; c += 4) {
            float4 q = xp[c >> 2];
            m[c] = q.x; m[c + 1] = q.y; m[c + 2] = q.z; m[c + 3] = q.w;
        }
        float sc = 0.f;
#pragma unroll
        for (int c = 0; c < C; c++) {
            float vv = m[c] + a_xr[c];
            vv = (vv > 0.f) ? vv : 0.2f * vv;
            sc = fmaf(vv, a_att[c], sc);
        }
        float p = v ? ex2f(sc * 1.44269504f) : 0.f;
        if (v) g_p[k] = p;
        S += p;
    }
#pragma unroll
    for (int o = 16; o; o >>= 1) S += __shfl_xor_sync(0xffffffffu, S, o);
    float rinv = __fdividef(1.f, S);
    float tl2e = tval * 1.44269504f;

    // pass 2: per-channel softmax-aggregation num/den in one sweep
    float num[C], den[C];
#pragma unroll
    for (int c = 0; c < C; c++) { num[c] = 0.f; den[c] = 0.f; }
    for (int k = beg + lane; k < kend; k += 32) {
        bool v = k < end;
        int s = v ? g_srcs[k] : 0;
        float m[C];
        const float4* xp = (const float4*)(xl + s * C);
#pragma unroll
        for (int c = 0; c < C; c += 4) {
            float4 q = xp[c >> 2];
            m[c] = q.x; m[c + 1] = q.y; m[c + 2] = q.z; m[c + 3] = q.w;
        }
        float p = v ? g_p[k] : 0.f;
        float alpha = p * rinv;
        float ul2 = alpha * tl2e;
        float vm = v ? 1.f : 0.f;
#pragma unroll
        for (int c = 0; c < C; c++) {
            float e = ex2f(m[c] * ul2) * vm;   // exp(t * m_c), masked
            float mm = m[c] * alpha;           // m_c
            den[c] += e;
            num[c] = fmaf(e, mm, num[c]);
        }
    }
#pragma unroll
    for (int o = 16; o; o >>= 1) {
#pragma unroll
        for (int c = 0; c < C; c++) {
            num[c] += __shfl_xor_sync(0xffffffffu, num[c], o);
            den[c] += __shfl_xor_sync(0xffffffffu, den[c], o);
        }
    }
    if (lane == 0) {
#pragma unroll
        for (int c = 0; c < C; c++) {
            float g = (den[c] > 0.f) ? __fdividef(num[c], den[c]) : 0.f;
            float hv = g + bias[c] + lin[warp * C + c];
            out[warp * C + c] = hv > 0.f ? hv : 0.f;
        }
    }
}

__global__ void __launch_bounds__(256) k_edge1(
    const float* __restrict__ att, const float* __restrict__ bias,
    const float* __restrict__ tptr)
{
    edge_impl<16>(g_xl1, g_xr1, att, bias, g_lin1, tptr, g_h);
}

__global__ void __launch_bounds__(256) k_edge2(
    const float* __restrict__ att, const float* __restrict__ bias,
    const float* __restrict__ tptr)
{
    edge_impl<8>(g_xl2, g_xr2, att, bias, g_lin2, tptr, g_h2);
}

// ---------------- MLP head + log_sigmoid ----------------
__global__ void __launch_bounds__(256) k_head(
    const float* __restrict__ W3, const float* __restrict__ b3,
    const float* __restrict__ W4, const float* __restrict__ b4,
    const float* __restrict__ W5, const float* __restrict__ b5,
    const float* __restrict__ Wout, const float* __restrict__ bout,
    float* __restrict__ out)
{
    int i = blockIdx.x * blockDim.x + threadIdx.x;
    if (i >= NN) return;
    const float4* gp = (const float4*)(g_h2 + i * 8);
    float4 q0 = gp[0], q1 = gp[1];
    float g[8] = {q0.x, q0.y, q0.z, q0.w, q1.x, q1.y, q1.z, q1.w};
    float s4 = b4[0];
#pragma unroll
    for (int c = 0; c < 8; c++) {
        float z = b3[c];
#pragma unroll
        for (int k = 0; k < 8; k++) z = fmaf(g[k], W3[k * 8 + c], z);
        z = z > 0.f ? z : 0.f;
        s4 = fmaf(z, W4[c], s4);
    }
    s4 = s4 > 0.f ? s4 : 0.f;
    float s5 = W5[0] * s4 + b5[0];
    s5 = s5 > 0.f ? s5 : 0.f;
    float xo = Wout[0] * s5 + bout[0];
    float ls = (xo >= 0.f) ? -log1pf(expf(-xo)) : (xo - log1pf(expf(xo)));
    out[i] = ls;
}

// ---------------- launch ----------------
extern "C" void kernel_launch(void* const* d_in, const int* in_sizes, int n_in,
                              void* d_out, int out_size)
{
    const float* x    = (const float*)d_in[0];
    const int*   ei   = (const int*)d_in[1];
    const int*   src  = ei;
    const int*   dst  = ei + EE;
    const float* Wl1  = (const float*)d_in[3];
    const float* Wr1  = (const float*)d_in[4];
    const float* att1 = (const float*)d_in[5];
    const float* b1   = (const float*)d_in[6];
    const float* Wlin1= (const float*)d_in[7];
    const float* blin1= (const float*)d_in[8];
    const float* Wl2  = (const float*)d_in[9];
    const float* Wr2  = (const float*)d_in[10];
    const float* att2 = (const float*)d_in[11];
    const float* b2   = (const float*)d_in[12];
    const float* Wlin2= (const float*)d_in[13];
    const float* blin2= (const float*)d_in[14];
    const float* t    = (const float*)d_in[15];
    const float* W3   = (const float*)d_in[16];
    const float* b3   = (const float*)d_in[17];
    const float* W4   = (const float*)d_in[18];
    const float* b4   = (const float*)d_in[19];
    const float* W5   = (const float*)d_in[20];
    const float* b5   = (const float*)d_in[21];
    const float* Wout = (const float*)d_in[22];
    const float* bout = (const float*)d_in[23];
    float* out = (float*)d_out;

    // CSR build (per launch, deterministic up to segment permutation)
    k_zero<<<(NN + 256) / 256, 256>>>();
    k_hist<<<(EE + 255) / 256, 256>>>(dst);
    k_scan1<<<NBLK, 512>>>();
    k_scan2<<<1, 32>>>();
    k_scan3<<<NBLK, 512>>>();
    k_scatter<<<(EE + 255) / 256, 256>>>(src, dst);

    // layer 1
    k_gemm1<<<(NN + 31) / 32, 256>>>(x, Wl1, Wr1, Wlin1, blin1);
    k_edge1<<<(NN + 7) / 8, 256>>>(att1, b1, t);

    // layer 2 (pool is identity: batch = arange(N))
    k_gemm2<<<(NN + 255) / 256, 256>>>(Wl2, Wr2, Wlin2, blin2);
    k_edge2<<<(NN + 7) / 8, 256>>>(att2, b2, t);

    // head
    k_head<<<(NN + 255) / 256, 256>>>(W3, b3, W4, b4, W5, b5, Wout, bout, out);
}

// round 2
// speedup vs baseline: 1.5508x; 1.5508x over previous
#include <cuda_runtime.h>

#define NN 100000
#define EE 3200000
#define FIN 128
#define NBLK 196        // ceil(NN/512)
#define MAXD1 64
#define MAXD2 64
#define L2E 1.44269504f

// ---------------- scratch (static device globals; no allocs) ----------------
__device__ int   g_cnt[NN + 1];
__device__ int   g_off[NN + 1];
__device__ int   g_cur[NN];
__device__ unsigned long long g_lb[NBLK];   // decoupled-lookback: (flag<<32)|value
__device__ int   g_srcs[EE];
__device__ float g_p[EE];                   // overflow-only attention weights
__device__ float g_xl1[NN * 16];
__device__ float g_xr1[NN * 16];
__device__ float g_lin1[NN * 16];
__device__ float g_h[NN * 16];
__device__ float g_xl2[NN * 8];
__device__ float g_xr2[NN * 8];
__device__ float g_lin2[NN * 8];
__device__ float g_h2[NN * 8];

__device__ __forceinline__ float ex2f(float x) {
    float y; asm("ex2.approx.f32 %0, %1;" : "=f"(y) : "f"(x)); return y;
}

// ---------------- CSR build ----------------
__global__ void k_zero() {
    int i = blockIdx.x * blockDim.x + threadIdx.x;
    if (i <= NN) g_cnt[i] = 0;
    if (i < NBLK) g_lb[i] = 0ull;
}

__global__ void k_hist(const int* __restrict__ dst) {
    int e = blockIdx.x * blockDim.x + threadIdx.x;
    if (e < EE) atomicAdd(&g_cnt[dst[e]], 1);
}

// single-pass scan with decoupled lookback
__global__ void __launch_bounds__(512) k_scan_lb() {
    int t = threadIdx.x, b = blockIdx.x;
    int i = b * 512 + t;
    int v = (i < NN) ? g_cnt[i] : 0;
    int lane = t & 31, wid = t >> 5;
    int incl = v;
#pragma unroll
    for (int o = 1; o < 32; o <<= 1) {
        int u = __shfl_up_sync(0xffffffffu, incl, o);
        if (lane >= o) incl += u;
    }
    __shared__ int ws[16];
    if (lane == 31) ws[wid] = incl;
    __syncthreads();
    if (t < 16) {
        int x = ws[t];
#pragma unroll
        for (int o = 1; o < 16; o <<= 1) {
            int u = __shfl_up_sync(0x0000ffffu, x, o);
            if (t >= o) x += u;
        }
        ws[t] = x;
    }
    __syncthreads();
    if (wid > 0) incl += ws[wid - 1];

    __shared__ int s_pfx;
    if (t == 511) {
        // publish aggregate
        atomicExch(&g_lb[b], (1ull << 32) | (unsigned)incl);
        int pfx = 0;
        for (int j = b - 1; j >= 0;) {
            unsigned long long u = atomicAdd(&g_lb[j], 0ull);
            unsigned f = (unsigned)(u >> 32);
            if (f == 0u) continue;
            pfx += (int)(u & 0xffffffffu);
            if (f == 2u) break;
            --j;
        }
        atomicExch(&g_lb[b], (2ull << 32) | (unsigned)(pfx + incl));
        s_pfx = pfx;
    }
    __syncthreads();
    if (i < NN) {
        int val = incl + s_pfx;
        g_off[i + 1] = val;
        g_cur[i] = val - v;
    }
    if (i == 0) g_off[0] = 0;
}

__global__ void k_scatter(const int* __restrict__ src, const int* __restrict__ dst) {
    int e = blockIdx.x * blockDim.x + threadIdx.x;
    if (e < EE) {
        int p = atomicAdd(&g_cur[dst[e]], 1);
        g_srcs[p] = src[e];
    }
}

// ---------------- layer-1 node GEMM: xl1 | xr1 | lin1(+blin1) ----------------
// block: 128 rows x 48 cols; thread: 4 rows x 6 cols; K tiled by 32
__global__ void __launch_bounds__(256) k_gemm1(
    const float* __restrict__ x, const float* __restrict__ Wl,
    const float* __restrict__ Wr, const float* __restrict__ Wlin,
    const float* __restrict__ blin)
{
    __shared__ float sx[128][36];   // 32 k + pad (stride %4==0 for float4)
    __shared__ float sw[32][48];
    int t = threadIdx.x;
    int cg = t & 7, rg = t >> 3;
    int c0 = cg * 6;
    int rowbase = blockIdx.x * 128;
    float acc[4][6];
#pragma unroll
    for (int i = 0; i < 4; i++)
#pragma unroll
        for (int j = 0; j < 6; j++) acc[i][j] = 0.f;

    for (int kb = 0; kb < FIN; kb += 32) {
        // load x tile (128x32) as float4, coalesced
#pragma unroll
        for (int n = 0; n < 4; n++) {
            int idx = t + n * 256;
            int r = idx >> 3, k4 = idx & 7;
            int gr = rowbase + r;
            float4 val = make_float4(0.f, 0.f, 0.f, 0.f);
            if (gr < NN) val = *(const float4*)(x + gr * FIN + kb + k4 * 4);
            *(float4*)&sx[r][k4 * 4] = val;
        }
        // load weight tile (32x48)
        for (int idx = t; idx < 32 * 48; idx += 256) {
            int k = idx / 48, j = idx % 48;
            int gk = kb + k;
            float val;
            if (j < 16)      val = Wl[gk * 16 + j];
            else if (j < 32) val = Wr[gk * 16 + j - 16];
            else             val = Wlin[gk * 16 + j - 32];
            sw[k][j] = val;
        }
        __syncthreads();
#pragma unroll
        for (int k = 0; k < 32; k += 4) {
            float xv[4][4];
#pragma unroll
            for (int i = 0; i < 4; i++) {
                float4 tmp = *(const float4*)&sx[rg * 4 + i][k];
                xv[i][0] = tmp.x; xv[i][1] = tmp.y; xv[i][2] = tmp.z; xv[i][3] = tmp.w;
            }
#pragma unroll
            for (int kk = 0; kk < 4; kk++) {
                float wv[6];
#pragma unroll
                for (int j = 0; j < 6; j++) wv[j] = sw[k + kk][c0 + j];
#pragma unroll
                for (int i = 0; i < 4; i++)
#pragma unroll
                    for (int j = 0; j < 6; j++)
                        acc[i][j] = fmaf(xv[i][kk], wv[j], acc[i][j]);
            }
        }
        __syncthreads();
    }
#pragma unroll
    for (int i = 0; i < 4; i++) {
        int gr = rowbase + rg * 4 + i;
        if (gr < NN) {
#pragma unroll
            for (int j = 0; j < 6; j++) {
                int c = c0 + j;
                if (c < 16)      g_xl1[gr * 16 + c] = acc[i][j];
                else if (c < 32) g_xr1[gr * 16 + (c - 16)] = acc[i][j];
                else             g_lin1[gr * 16 + (c - 32)] = acc[i][j] + blin[c - 32];
            }
        }
    }
}

// ---------------- layer-2 node GEMM ----------------
__global__ void __launch_bounds__(256) k_gemm2(
    const float* __restrict__ Wl, const float* __restrict__ Wr,
    const float* __restrict__ Wlin, const float* __restrict__ blin)
{
    __shared__ float sw[16 * 24];
    int t = threadIdx.x;
    for (int idx = t; idx < 16 * 24; idx += 256) {
        int k = idx / 24, j = idx % 24;
        float v;
        if (j < 8)       v = Wl[k * 8 + j];
        else if (j < 16) v = Wr[k * 8 + j - 8];
        else             v = Wlin[k * 8 + j - 16];
        sw[idx] = v;
    }
    __syncthreads();
    int i = blockIdx.x * blockDim.x + t;
    if (i >= NN) return;
    const float4* hp = (const float4*)(g_h + i * 16);
    float4 q0 = hp[0], q1 = hp[1], q2 = hp[2], q3 = hp[3];
    float h[16] = {q0.x, q0.y, q0.z, q0.w, q1.x, q1.y, q1.z, q1.w,
                   q2.x, q2.y, q2.z, q2.w, q3.x, q3.y, q3.z, q3.w};
    float acc[24];
#pragma unroll
    for (int j = 0; j < 24; j++) acc[j] = 0.f;
#pragma unroll
    for (int k = 0; k < 16; k++) {
        float hv = h[k];
#pragma unroll
        for (int j = 0; j < 24; j++) acc[j] = fmaf(hv, sw[k * 24 + j], acc[j]);
    }
#pragma unroll
    for (int j = 0; j < 8; j++) {
        g_xl2[i * 8 + j] = acc[j];
        g_xr2[i * 8 + j] = acc[8 + j];
        g_lin2[i * 8 + j] = acc[16 + j] + blin[j];
    }
}

// ---------------- edge kernel layer 1: warp/node, 4 lanes/edge ----------------
__global__ void __launch_bounds__(256) k_edge1(
    const float* __restrict__ att, const float* __restrict__ bias,
    const float* __restrict__ tptr)
{
    __shared__ float4 sm_m[8][MAXD1][4];
    __shared__ float  sm_p[8][MAXD1];
    int w = threadIdx.x >> 5;
    int lane = threadIdx.x & 31;
    int node = blockIdx.x * 8 + w;
    if (node >= NN) return;
    int q = lane & 3, e8 = lane >> 2;
    int beg = g_off[node], end = g_off[node + 1];
    int deg = end - beg;
    float4 a_att = *(const float4*)(att + q * 4);
    float4 a_xr  = *(const float4*)(g_xr1 + node * 16 + q * 4);
    float tval = tptr[0];
    int ngroups = (deg + 7) >> 3;

    // pass 1: scores -> p, cache m & p in smem, accumulate S
    float S = 0.f;
    for (int it = 0; it < ngroups; it++) {
        int kbase = beg + it * 8;
        int sv = 0;
        if (lane < 8 && kbase + lane < end) sv = g_srcs[kbase + lane];
        int myk = kbase + e8;
        bool v = myk < end;
        int s = __shfl_sync(0xffffffffu, sv, e8);
        float4 mq = make_float4(0.f, 0.f, 0.f, 0.f);
        if (v) mq = *(const float4*)(g_xl1 + s * 16 + q * 4);
        float y0 = mq.x + a_xr.x; y0 = fmaxf(y0, 0.2f * y0);
        float y1 = mq.y + a_xr.y; y1 = fmaxf(y1, 0.2f * y1);
        float y2 = mq.z + a_xr.z; y2 = fmaxf(y2, 0.2f * y2);
        float y3 = mq.w + a_xr.w; y3 = fmaxf(y3, 0.2f * y3);
        float sc = y0 * a_att.x;
        sc = fmaf(y1, a_att.y, sc);
        sc = fmaf(y2, a_att.z, sc);
        sc = fmaf(y3, a_att.w, sc);
        sc += __shfl_xor_sync(0xffffffffu, sc, 1);
        sc += __shfl_xor_sync(0xffffffffu, sc, 2);
        float p = v ? ex2f(sc * L2E) : 0.f;
        int slot = it * 8 + e8;
        if (slot < MAXD1) {
            sm_m[w][slot][q] = mq;
            if (q == 0) sm_p[w][slot] = p;
        } else if (v && q == 0) {
            g_p[myk] = p;
        }
        if (q == 0) S += p;
    }
#pragma unroll
    for (int o = 16; o; o >>= 1) S += __shfl_xor_sync(0xffffffffu, S, o);
    float rinv = __fdividef(1.f, S);
    float tl2e = tval * L2E;
    __syncwarp();

    // pass 2: fused softmax-aggregation numerator/denominator
    float4 num = make_float4(0.f, 0.f, 0.f, 0.f);
    float4 den = make_float4(0.f, 0.f, 0.f, 0.f);
    for (int it = 0; it < ngroups; it++) {
        int kbase = beg + it * 8;
        int myk = kbase + e8;
        bool v = myk < end;
        int slot = it * 8 + e8;
        float4 mq; float p;
        if (slot < MAXD1) {
            mq = sm_m[w][slot][q];
            p = sm_p[w][slot];
        } else {
            int sv = 0;
            if (lane < 8 && kbase + lane < end) sv = g_srcs[kbase + lane];
            int s = __shfl_sync(0xffffffffu, sv, e8);
            mq = make_float4(0.f, 0.f, 0.f, 0.f);
            p = 0.f;
            if (v) { mq = *(const float4*)(g_xl1 + s * 16 + q * 4); p = g_p[myk]; }
        }
        float vm = v ? 1.f : 0.f;
        float a = p * rinv;
        float we = a * tl2e;
        float e0 = ex2f(mq.x * we) * vm;
        float e1 = ex2f(mq.y * we) * vm;
        float e2 = ex2f(mq.z * we) * vm;
        float e3 = ex2f(mq.w * we) * vm;
        den.x += e0; den.y += e1; den.z += e2; den.w += e3;
        num.x = fmaf(e0, mq.x * a, num.x);
        num.y = fmaf(e1, mq.y * a, num.y);
        num.z = fmaf(e2, mq.z * a, num.z);
        num.w = fmaf(e3, mq.w * a, num.w);
    }
#pragma unroll
    for (int o = 4; o < 32; o <<= 1) {
        num.x += __shfl_xor_sync(0xffffffffu, num.x, o);
        num.y += __shfl_xor_sync(0xffffffffu, num.y, o);
        num.z += __shfl_xor_sync(0xffffffffu, num.z, o);
        num.w += __shfl_xor_sync(0xffffffffu, num.w, o);
        den.x += __shfl_xor_sync(0xffffffffu, den.x, o);
        den.y += __shfl_xor_sync(0xffffffffu, den.y, o);
        den.z += __shfl_xor_sync(0xffffffffu, den.z, o);
        den.w += __shfl_xor_sync(0xffffffffu, den.w, o);
    }
    if (e8 == 0) {
        float4 b4 = *(const float4*)(bias + q * 4);
        float4 l4 = *(const float4*)(g_lin1 + node * 16 + q * 4);
        float4 o4;
        float g0 = (den.x > 0.f) ? __fdividef(num.x, den.x) : 0.f;
        float g1 = (den.y > 0.f) ? __fdividef(num.y, den.y) : 0.f;
        float g2v = (den.z > 0.f) ? __fdividef(num.z, den.z) : 0.f;
        float g3 = (den.w > 0.f) ? __fdividef(num.w, den.w) : 0.f;
        o4.x = fmaxf(g0 + b4.x + l4.x, 0.f);
        o4.y = fmaxf(g1 + b4.y + l4.y, 0.f);
        o4.z = fmaxf(g2v + b4.z + l4.z, 0.f);
        o4.w = fmaxf(g3 + b4.w + l4.w, 0.f);
        *(float4*)(g_h + node * 16 + q * 4) = o4;
    }
}

// ---------------- edge kernel layer 2: warp/node, 2 lanes/edge ----------------
__global__ void __launch_bounds__(256) k_edge2(
    const float* __restrict__ att, const float* __restrict__ bias,
    const float* __restrict__ tptr)
{
    __shared__ float4 sm_m[8][MAXD2][2];
    __shared__ float  sm_p[8][MAXD2];
    int w = threadIdx.x >> 5;
    int lane = threadIdx.x & 31;
    int node = blockIdx.x * 8 + w;
    if (node >= NN) return;
    int q = lane & 1, e16 = lane >> 1;
    int beg = g_off[node], end = g_off[node + 1];
    int deg = end - beg;
    float4 a_att = *(const float4*)(att + q * 4);
    float4 a_xr  = *(const float4*)(g_xr2 + node * 8 + q * 4);
    float tval = tptr[0];
    int ngroups = (deg + 15) >> 4;

    float S = 0.f;
    for (int it = 0; it < ngroups; it++) {
        int kbase = beg + it * 16;
        int sv = 0;
        if (lane < 16 && kbase + lane < end) sv = g_srcs[kbase + lane];
        int myk = kbase + e16;
        bool v = myk < end;
        int s = __shfl_sync(0xffffffffu, sv, e16);
        float4 mq = make_float4(0.f, 0.f, 0.f, 0.f);
        if (v) mq = *(const float4*)(g_xl2 + s * 8 + q * 4);
        float y0 = mq.x + a_xr.x; y0 = fmaxf(y0, 0.2f * y0);
        float y1 = mq.y + a_xr.y; y1 = fmaxf(y1, 0.2f * y1);
        float y2 = mq.z + a_xr.z; y2 = fmaxf(y2, 0.2f * y2);
        float y3 = mq.w + a_xr.w; y3 = fmaxf(y3, 0.2f * y3);
        float sc = y0 * a_att.x;
        sc = fmaf(y1, a_att.y, sc);
        sc = fmaf(y2, a_att.z, sc);
        sc = fmaf(y3, a_att.w, sc);
        sc += __shfl_xor_sync(0xffffffffu, sc, 1);
        float p = v ? ex2f(sc * L2E) : 0.f;
        int slot = it * 16 + e16;
        if (slot < MAXD2) {
            sm_m[w][slot][q] = mq;
            if (q == 0) sm_p[w][slot] = p;
        } else if (v && q == 0) {
            g_p[myk] = p;
        }
        if (q == 0) S += p;
    }
#pragma unroll
    for (int o = 16; o; o >>= 1) S += __shfl_xor_sync(0xffffffffu, S, o);
    float rinv = __fdividef(1.f, S);
    float tl2e = tval * L2E;
    __syncwarp();

    float4 num = make_float4(0.f, 0.f, 0.f, 0.f);
    float4 den = make_float4(0.f, 0.f, 0.f, 0.f);
    for (int it = 0; it < ngroups; it++) {
        int kbase = beg + it * 16;
        int myk = kbase + e16;
        bool v = myk < end;
        int slot = it * 16 + e16;
        float4 mq; float p;
        if (slot < MAXD2) {
            mq = sm_m[w][slot][q];
            p = sm_p[w][slot];
        } else {
            int sv = 0;
            if (lane < 16 && kbase + lane < end) sv = g_srcs[kbase + lane];
            int s = __shfl_sync(0xffffffffu, sv, e16);
            mq = make_float4(0.f, 0.f, 0.f, 0.f);
            p = 0.f;
            if (v) { mq = *(const float4*)(g_xl2 + s * 8 + q * 4); p = g_p[myk]; }
        }
        float vm = v ? 1.f : 0.f;
        float a = p * rinv;
        float we = a * tl2e;
        float e0 = ex2f(mq.x * we) * vm;
        float e1 = ex2f(mq.y * we) * vm;
        float e2 = ex2f(mq.z * we) * vm;
        float e3 = ex2f(mq.w * we) * vm;
        den.x += e0; den.y += e1; den.z += e2; den.w += e3;
        num.x = fmaf(e0, mq.x * a, num.x);
        num.y = fmaf(e1, mq.y * a, num.y);
        num.z = fmaf(e2, mq.z * a, num.z);
        num.w = fmaf(e3, mq.w * a, num.w);
    }
#pragma unroll
    for (int o = 2; o < 32; o <<= 1) {
        num.x += __shfl_xor_sync(0xffffffffu, num.x, o);
        num.y += __shfl_xor_sync(0xffffffffu, num.y, o);
        num.z += __shfl_xor_sync(0xffffffffu, num.z, o);
        num.w += __shfl_xor_sync(0xffffffffu, num.w, o);
        den.x += __shfl_xor_sync(0xffffffffu, den.x, o);
        den.y += __shfl_xor_sync(0xffffffffu, den.y, o);
        den.z += __shfl_xor_sync(0xffffffffu, den.z, o);
        den.w += __shfl_xor_sync(0xffffffffu, den.w, o);
    }
    if (e16 == 0) {
        float4 b4 = *(const float4*)(bias + q * 4);
        float4 l4 = *(const float4*)(g_lin2 + node * 8 + q * 4);
        float4 o4;
        float g0 = (den.x > 0.f) ? __fdividef(num.x, den.x) : 0.f;
        float g1 = (den.y > 0.f) ? __fdividef(num.y, den.y) : 0.f;
        float g2v = (den.z > 0.f) ? __fdividef(num.z, den.z) : 0.f;
        float g3 = (den.w > 0.f) ? __fdividef(num.w, den.w) : 0.f;
        o4.x = fmaxf(g0 + b4.x + l4.x, 0.f);
        o4.y = fmaxf(g1 + b4.y + l4.y, 0.f);
        o4.z = fmaxf(g2v + b4.z + l4.z, 0.f);
        o4.w = fmaxf(g3 + b4.w + l4.w, 0.f);
        *(float4*)(g_h2 + node * 8 + q * 4) = o4;
    }
}

// ---------------- MLP head + log_sigmoid ----------------
__global__ void __launch_bounds__(256) k_head(
    const float* __restrict__ W3, const float* __restrict__ b3,
    const float* __restrict__ W4, const float* __restrict__ b4,
    const float* __restrict__ W5, const float* __restrict__ b5,
    const float* __restrict__ Wout, const float* __restrict__ bout,
    float* __restrict__ out)
{
    int i = blockIdx.x * blockDim.x + threadIdx.x;
    if (i >= NN) return;
    const float4* gp = (const float4*)(g_h2 + i * 8);
    float4 q0 = gp[0], q1 = gp[1];
    float g[8] = {q0.x, q0.y, q0.z, q0.w, q1.x, q1.y, q1.z, q1.w};
    float s4 = b4[0];
#pragma unroll
    for (int c = 0; c < 8; c++) {
        float z = b3[c];
#pragma unroll
        for (int k = 0; k < 8; k++) z = fmaf(g[k], W3[k * 8 + c], z);
        z = z > 0.f ? z : 0.f;
        s4 = fmaf(z, W4[c], s4);
    }
    s4 = s4 > 0.f ? s4 : 0.f;
    float s5 = W5[0] * s4 + b5[0];
    s5 = s5 > 0.f ? s5 : 0.f;
    float xo = Wout[0] * s5 + bout[0];
    float ls = (xo >= 0.f) ? -log1pf(expf(-xo)) : (xo - log1pf(expf(xo)));
    out[i] = ls;
}

// ---------------- launch ----------------
extern "C" void kernel_launch(void* const* d_in, const int* in_sizes, int n_in,
                              void* d_out, int out_size)
{
    const float* x    = (const float*)d_in[0];
    const int*   ei   = (const int*)d_in[1];
    const int*   src  = ei;
    const int*   dst  = ei + EE;
    const float* Wl1  = (const float*)d_in[3];
    const float* Wr1  = (const float*)d_in[4];
    const float* att1 = (const float*)d_in[5];
    const float* b1   = (const float*)d_in[6];
    const float* Wlin1= (const float*)d_in[7];
    const float* blin1= (const float*)d_in[8];
    const float* Wl2  = (const float*)d_in[9];
    const float* Wr2  = (const float*)d_in[10];
    const float* att2 = (const float*)d_in[11];
    const float* b2   = (const float*)d_in[12];
    const float* Wlin2= (const float*)d_in[13];
    const float* blin2= (const float*)d_in[14];
    const float* t    = (const float*)d_in[15];
    const float* W3   = (const float*)d_in[16];
    const float* b3   = (const float*)d_in[17];
    const float* W4   = (const float*)d_in[18];
    const float* b4   = (const float*)d_in[19];
    const float* W5   = (const float*)d_in[20];
    const float* b5   = (const float*)d_in[21];
    const float* Wout = (const float*)d_in[22];
    const float* bout = (const float*)d_in[23];
    float* out = (float*)d_out;

    // CSR build: 4 launches (0-3)
    k_zero<<<(NN + 256) / 256, 256>>>();
    k_hist<<<(EE + 255) / 256, 256>>>(dst);
    k_scan_lb<<<NBLK, 512>>>();
    k_scatter<<<(EE + 255) / 256, 256>>>(src, dst);

    // layer 1 (launches 4, 5 -> ncu -s 5 captures k_edge1)
    k_gemm1<<<(NN + 127) / 128, 256>>>(x, Wl1, Wr1, Wlin1, blin1);
    k_edge1<<<(NN + 7) / 8, 256>>>(att1, b1, t);

    // layer 2 (pool is identity: batch = arange(N))
    k_gemm2<<<(NN + 255) / 256, 256>>>(Wl2, Wr2, Wlin2, blin2);
    k_edge2<<<(NN + 7) / 8, 256>>>(att2, b2, t);

    // head
    k_head<<<(NN + 255) / 256, 256>>>(W3, b3, W4, b4, W5, b5, Wout, bout, out);
}